// round 13
// baseline (speedup 1.0000x reference)
#include <cuda_runtime.h>
#include <cstdint>
#include <math.h>

#define B_ 4
#define T_ 2048
#define EMB_ 2048
#define HD_ 128
#define HALF_ 64
#define SCALE_ 0.08838834764831845f   // 1/sqrt(128)

// __device__ scratch (allocation-free rule)
__device__ float g_Q[B_ * T_ * HD_];
__device__ float g_K[B_ * T_ * HD_];
__device__ float g_V[B_ * T_ * HD_];
// split-KV partials: [b][qt][chunk][64 rows][128] + m,l per row
__device__ float g_pO[B_ * 32 * 4 * 64 * HD_];
__device__ float g_pM[B_ * 32 * 4 * 64];
__device__ float g_pL[B_ * 32 * 4 * 64];

__device__ __forceinline__ uint32_t to_tf32_bits(float v) {
    uint32_t r;
    asm("{ .reg .b32 t; cvt.rna.tf32.f32 t, %1; mov.b32 %0, t; }" : "=r"(r) : "f"(v));
    return r;
}

__device__ __forceinline__ void mma_tf32(float* c, const uint32_t* a, const uint32_t* b) {
    asm volatile(
        "mma.sync.aligned.m16n8k8.row.col.f32.tf32.tf32.f32 "
        "{%0,%1,%2,%3}, {%4,%5,%6,%7}, {%8,%9}, {%0,%1,%2,%3};"
        : "+f"(c[0]), "+f"(c[1]), "+f"(c[2]), "+f"(c[3])
        : "r"(a[0]), "r"(a[1]), "r"(a[2]), "r"(a[3]), "r"(b[0]), "r"(b[1]));
}

// ---------------------------------------------------------------------------
// Kernel A: QKV projection via mma.sync tf32 + RoPE epilogue. (R8 version:
// single-buffered, static smem 35.8KB; 2 CTAs/SM co-resident overlap phases.)
// grid (64, 3). 256 threads = 8 warps (4M x 2N); warp tile 32x64.
// ---------------------------------------------------------------------------
__global__ __launch_bounds__(256, 2) void qkv_mma(
    const float* __restrict__ x,  const float* __restrict__ Wq,
    const float* __restrict__ Wk, const float* __restrict__ Wv,
    const float* __restrict__ rc, const float* __restrict__ rs)
{
    __shared__ uint32_t As[128][36];   // [m][k], pad 36: frag loads bank 4*gid+tig
    __shared__ uint32_t Bs[32][136];   // [k][n], pad 136: frag loads bank 8*tig+gid

    const int which = blockIdx.y;
    const float* W = (which == 0) ? Wq : (which == 1) ? Wk : Wv;
    float* out     = (which == 0) ? g_Q : (which == 1) ? g_K : g_V;
    const int m0   = blockIdx.x * 128;

    const int tid  = threadIdx.x;
    const int wid  = tid >> 5, lane = tid & 31;
    const int gid  = lane >> 2, tig = lane & 3;
    const int wm   = (wid >> 1) * 32;     // warp row base
    const int wn   = (wid & 1) * 64;      // warp col base

    float acc[2][8][4];
#pragma unroll
    for (int mt = 0; mt < 2; mt++)
#pragma unroll
        for (int nt = 0; nt < 8; nt++)
#pragma unroll
            for (int q = 0; q < 4; q++) acc[mt][nt][q] = 0.f;

    for (int c = 0; c < 64; c++) {
        const float* xs = x + (size_t)m0 * EMB_ + c * 32;
        const float* ws = W + (size_t)(c * 32) * HD_;
#pragma unroll
        for (int it = 0; it < 4; it++) {
            int idx = it * 256 + tid;
            int m = idx >> 3, kk = (idx & 7) << 2;
            float4 v = *(const float4*)(xs + (size_t)m * EMB_ + kk);
            uint4 u = make_uint4(to_tf32_bits(v.x), to_tf32_bits(v.y),
                                 to_tf32_bits(v.z), to_tf32_bits(v.w));
            *(uint4*)&As[m][kk] = u;
        }
#pragma unroll
        for (int it = 0; it < 4; it++) {
            int idx = it * 256 + tid;
            int kk = idx >> 5, n = (idx & 31) << 2;
            float4 v = *(const float4*)(ws + (size_t)kk * HD_ + n);
            uint4 u = make_uint4(to_tf32_bits(v.x), to_tf32_bits(v.y),
                                 to_tf32_bits(v.z), to_tf32_bits(v.w));
            *(uint4*)&Bs[kk][n] = u;
        }
        __syncthreads();

#pragma unroll
        for (int s = 0; s < 4; s++) {          // K=8 slices
            const int kb = s * 8;
            uint32_t a[2][4], b[8][2];
#pragma unroll
            for (int mt = 0; mt < 2; mt++) {
                int mrow = wm + mt * 16 + gid;
                a[mt][0] = As[mrow][kb + tig];
                a[mt][1] = As[mrow + 8][kb + tig];
                a[mt][2] = As[mrow][kb + tig + 4];
                a[mt][3] = As[mrow + 8][kb + tig + 4];
            }
#pragma unroll
            for (int nt = 0; nt < 8; nt++) {
                int ncol = wn + nt * 8 + gid;
                b[nt][0] = Bs[kb + tig][ncol];
                b[nt][1] = Bs[kb + tig + 4][ncol];
            }
#pragma unroll
            for (int mt = 0; mt < 2; mt++)
#pragma unroll
                for (int nt = 0; nt < 8; nt++)
                    mma_tf32(acc[mt][nt], a[mt], b[nt]);
        }
        __syncthreads();
    }

    // Epilogue: RoPE pairs fall out of the C fragment layout.
#pragma unroll
    for (int mt = 0; mt < 2; mt++) {
#pragma unroll
        for (int half = 0; half < 2; half++) {
            int row = m0 + wm + mt * 16 + gid + half * 8;
            int t = row & (T_ - 1);
#pragma unroll
            for (int nt = 0; nt < 8; nt++) {
                int col = wn + nt * 8 + tig * 2;
                float re = acc[mt][nt][half * 2];
                float im = acc[mt][nt][half * 2 + 1];
                if (which < 2) {
                    float co = rc[t * HALF_ + (col >> 1)];
                    float si = rs[t * HALF_ + (col >> 1)];
                    float nre = re * co - im * si;
                    float nim = re * si + im * co;
                    re = nre; im = nim;
                }
                *(float2*)(out + (size_t)row * HD_ + col) = make_float2(re, im);
            }
        }
    }
}

// ---------------------------------------------------------------------------
// Kernel B1: flash attention phase 1 (mma.sync tf32, split-KV chunks of 512).
// grid (80, 4): x = work item (qt, chunk), y = batch. 256 threads = 8 warps.
// S phase:  warp (wr=w>>1, wc=w&1): q-rows [16wr,+16), kv-cols [32wc,+32).
// PV phase: warp (wr, wc): q-rows [16wr,+16), hd-cols [64wc,+64).
// Cross-warp softmax combine via redM/redS smem slots.
// ---------------------------------------------------------------------------
__global__ __launch_bounds__(256) void attn_p1(float* __restrict__ out)
{
    extern __shared__ uint32_t dyn[];
    uint32_t* Qs = dyn;              // [64][132] tf32 bits
    uint32_t* Ks = Qs + 64 * 132;    // [64][132]
    uint32_t* Vs = Ks + 64 * 132;    // [64][136]
    uint32_t* Ps = Vs + 64 * 136;    // [64][68]
    float*   red = (float*)(Ps + 64 * 68);   // redM[2][64], redS[2][64]

    const int tid = threadIdx.x;
    const int w = tid >> 5, lane = tid & 31;
    const int gid = lane >> 2, tig = lane & 3;
    const int wr = w >> 1, wc = w & 1;
    const int b = blockIdx.y;
    const int i = blockIdx.x;

    int qt, c;
    if (i < 8)       { qt = i;                 c = 0; }
    else if (i < 24) { qt = 8 + (i - 8) / 2;   c = (i - 8) % 2; }
    else if (i < 48) { qt = 16 + (i - 24) / 3; c = (i - 24) % 3; }
    else             { qt = 24 + (i - 48) / 4; c = (i - 48) % 4; }
    const int kv_begin = c * 512;
    const int kv_end   = min((qt + 1) * 64, kv_begin + 512);
    const int niter    = (kv_end - kv_begin) >> 6;
    const int nch      = (qt >> 3) + 1;       // ceil((qt+1)/8)

    const float* gQ = g_Q + (size_t)b * T_ * HD_;
    const float* gK = g_K + (size_t)b * T_ * HD_;
    const float* gV = g_V + (size_t)b * T_ * HD_;

    // Load Q tile (scaled, tf32)
#pragma unroll
    for (int it = 0; it < 8; it++) {
        int idx = it * 256 + tid;
        int r = idx >> 5, c4 = idx & 31;
        float4 v = *(const float4*)(gQ + (size_t)(qt * 64 + r) * HD_ + c4 * 4);
        uint4 u = make_uint4(to_tf32_bits(v.x * SCALE_), to_tf32_bits(v.y * SCALE_),
                             to_tf32_bits(v.z * SCALE_), to_tf32_bits(v.w * SCALE_));
        *(uint4*)&Qs[r * 132 + c4 * 4] = u;
    }

    float o[8][4];
#pragma unroll
    for (int nt = 0; nt < 8; nt++)
#pragma unroll
        for (int q = 0; q < 4; q++) o[nt][q] = 0.f;
    float m0 = -1e30f, m1 = -1e30f, l0 = 0.f, l1 = 0.f;

    const int rl0 = wr * 16 + gid;            // local q rows of this thread
    const int rl1 = rl0 + 8;
    const int row0g = qt * 64 + rl0;
    const int row1g = qt * 64 + rl1;

    for (int itkv = 0; itkv < niter; itkv++) {
        const int kv0 = kv_begin + itkv * 64;
        // load K, V tiles (tf32)
#pragma unroll
        for (int it = 0; it < 8; it++) {
            int idx = it * 256 + tid;
            int r = idx >> 5, c4 = idx & 31;
            float4 kv = *(const float4*)(gK + (size_t)(kv0 + r) * HD_ + c4 * 4);
            *(uint4*)&Ks[r * 132 + c4 * 4] =
                make_uint4(to_tf32_bits(kv.x), to_tf32_bits(kv.y),
                           to_tf32_bits(kv.z), to_tf32_bits(kv.w));
            float4 vv = *(const float4*)(gV + (size_t)(kv0 + r) * HD_ + c4 * 4);
            *(uint4*)&Vs[r * 136 + c4 * 4] =
                make_uint4(to_tf32_bits(vv.x), to_tf32_bits(vv.y),
                           to_tf32_bits(vv.z), to_tf32_bits(vv.w));
        }
        __syncthreads();

        // S = Q K^T : warp computes 16 rows x 32 cols
        float s[4][4];
#pragma unroll
        for (int nt = 0; nt < 4; nt++)
#pragma unroll
            for (int q = 0; q < 4; q++) s[nt][q] = 0.f;
#pragma unroll
        for (int ks = 0; ks < 16; ks++) {
            uint32_t a[4];
            const int ar = rl0 * 132 + ks * 8 + tig;
            a[0] = Qs[ar];
            a[1] = Qs[ar + 8 * 132];
            a[2] = Qs[ar + 4];
            a[3] = Qs[ar + 8 * 132 + 4];
#pragma unroll
            for (int nt = 0; nt < 4; nt++) {
                uint32_t bfr[2];
                const int br = (wc * 32 + nt * 8 + gid) * 132 + ks * 8 + tig;
                bfr[0] = Ks[br];
                bfr[1] = Ks[br + 4];
                mma_tf32(s[nt], a, bfr);
            }
        }

        // causal mask (only near the diagonal)
        if (kv0 + 63 > qt * 64 + wr * 16) {
#pragma unroll
            for (int nt = 0; nt < 4; nt++) {
                int col = kv0 + wc * 32 + nt * 8 + 2 * tig;
                if (col > row0g)     s[nt][0] = -1e30f;
                if (col + 1 > row0g) s[nt][1] = -1e30f;
                if (col > row1g)     s[nt][2] = -1e30f;
                if (col + 1 > row1g) s[nt][3] = -1e30f;
            }
        }

        // local (half-row) max, intra-warp reduce over tig lanes
        float mr0 = -1e30f, mr1 = -1e30f;
#pragma unroll
        for (int nt = 0; nt < 4; nt++) {
            mr0 = fmaxf(mr0, fmaxf(s[nt][0], s[nt][1]));
            mr1 = fmaxf(mr1, fmaxf(s[nt][2], s[nt][3]));
        }
        mr0 = fmaxf(mr0, __shfl_xor_sync(0xffffffffu, mr0, 1));
        mr0 = fmaxf(mr0, __shfl_xor_sync(0xffffffffu, mr0, 2));
        mr1 = fmaxf(mr1, __shfl_xor_sync(0xffffffffu, mr1, 1));
        mr1 = fmaxf(mr1, __shfl_xor_sync(0xffffffffu, mr1, 2));
        if (tig == 0) {
            red[wc * 64 + rl0] = mr0;
            red[wc * 64 + rl1] = mr1;
        }
        __syncthreads();
        mr0 = fmaxf(red[rl0], red[64 + rl0]);
        mr1 = fmaxf(red[rl1], red[64 + rl1]);

        float mn0 = fmaxf(m0, mr0), mn1 = fmaxf(m1, mr1);
        float al0 = __expf(m0 - mn0), al1 = __expf(m1 - mn1);
        float sum0 = 0.f, sum1 = 0.f;
#pragma unroll
        for (int nt = 0; nt < 4; nt++) {
            float p0 = __expf(s[nt][0] - mn0);
            float p1 = __expf(s[nt][1] - mn0);
            float p2 = __expf(s[nt][2] - mn1);
            float p3 = __expf(s[nt][3] - mn1);
            sum0 += p0 + p1; sum1 += p2 + p3;
            const int pc = wc * 32 + nt * 8 + 2 * tig;
            *(uint2*)&Ps[rl0 * 68 + pc] = make_uint2(to_tf32_bits(p0), to_tf32_bits(p1));
            *(uint2*)&Ps[rl1 * 68 + pc] = make_uint2(to_tf32_bits(p2), to_tf32_bits(p3));
        }
        sum0 += __shfl_xor_sync(0xffffffffu, sum0, 1);
        sum0 += __shfl_xor_sync(0xffffffffu, sum0, 2);
        sum1 += __shfl_xor_sync(0xffffffffu, sum1, 1);
        sum1 += __shfl_xor_sync(0xffffffffu, sum1, 2);
        if (tig == 0) {
            red[128 + wc * 64 + rl0] = sum0;
            red[128 + wc * 64 + rl1] = sum1;
        }
        __syncthreads();
        sum0 = red[128 + rl0] + red[128 + 64 + rl0];
        sum1 = red[128 + rl1] + red[128 + 64 + rl1];
        l0 = l0 * al0 + sum0;  l1 = l1 * al1 + sum1;
        m0 = mn0;  m1 = mn1;

        // rescale O, then O += P @ V (warp: 16 rows x 64 hd-cols at 64*wc)
#pragma unroll
        for (int nt = 0; nt < 8; nt++) {
            o[nt][0] *= al0; o[nt][1] *= al0;
            o[nt][2] *= al1; o[nt][3] *= al1;
        }
#pragma unroll
        for (int ks = 0; ks < 8; ks++) {
            uint32_t a[4];
            const int ar = rl0 * 68 + ks * 8 + tig;
            a[0] = Ps[ar];
            a[1] = Ps[ar + 8 * 68];
            a[2] = Ps[ar + 4];
            a[3] = Ps[ar + 8 * 68 + 4];
#pragma unroll
            for (int nt = 0; nt < 8; nt++) {
                uint32_t bfr[2];
                const int br = (ks * 8 + tig) * 136 + wc * 64 + nt * 8 + gid;
                bfr[0] = Vs[br];
                bfr[1] = Vs[br + 4 * 136];
                mma_tf32(o[nt], a, bfr);
            }
        }
        __syncthreads();
    }

    // epilogue
    if (nch == 1) {
        float inv0 = 1.f / l0, inv1 = 1.f / l1;
        float* dst = out + (size_t)b * T_ * HD_;
#pragma unroll
        for (int nt = 0; nt < 8; nt++) {
            int col = wc * 64 + nt * 8 + 2 * tig;
            *(float2*)(dst + (size_t)(qt * 64 + rl0) * HD_ + col) =
                make_float2(o[nt][0] * inv0, o[nt][1] * inv0);
            *(float2*)(dst + (size_t)(qt * 64 + rl1) * HD_ + col) =
                make_float2(o[nt][2] * inv1, o[nt][3] * inv1);
        }
    } else {
        const size_t sb = ((size_t)((b * 32 + qt) * 4 + c)) * 64;
        float* pO = g_pO + sb * HD_;
#pragma unroll
        for (int nt = 0; nt < 8; nt++) {
            int col = wc * 64 + nt * 8 + 2 * tig;
            *(float2*)(pO + (size_t)rl0 * HD_ + col) = make_float2(o[nt][0], o[nt][1]);
            *(float2*)(pO + (size_t)rl1 * HD_ + col) = make_float2(o[nt][2], o[nt][3]);
        }
        if (wc == 0 && tig == 0) {
            g_pM[sb + rl0] = m0;  g_pL[sb + rl0] = l0;
            g_pM[sb + rl1] = m1;  g_pL[sb + rl1] = l1;
        }
    }
}

// ---------------------------------------------------------------------------
// Kernel B2: combine split-KV partials for qt >= 8. grid (24, 4), 256 threads.
// ---------------------------------------------------------------------------
__global__ __launch_bounds__(256) void attn_p2(float* __restrict__ out)
{
    const int qt = 8 + blockIdx.x;
    const int b  = blockIdx.y;
    const int nch = (qt >> 3) + 1;          // 2..4
    const int tid = threadIdx.x;
    const int r = tid >> 2, q4 = tid & 3;

    const size_t mlb = ((size_t)(b * 32 + qt) * 4) * 64 + r;
    float mv[4], lv[4];
    float M = -1e30f;
    for (int i = 0; i < nch; i++) {
        mv[i] = g_pM[mlb + (size_t)i * 64];
        lv[i] = g_pL[mlb + (size_t)i * 64];
        M = fmaxf(M, mv[i]);
    }
    float L = 0.f, wgt[4];
    for (int i = 0; i < nch; i++) {
        wgt[i] = __expf(mv[i] - M);
        L += wgt[i] * lv[i];
    }
    const float invL = 1.f / L;

    float4 acc[8];
#pragma unroll
    for (int j = 0; j < 8; j++) acc[j] = make_float4(0.f, 0.f, 0.f, 0.f);
    for (int i = 0; i < nch; i++) {
        const float* src = g_pO +
            (((size_t)((b * 32 + qt) * 4 + i)) * 64 + r) * HD_ + q4 * 32;
        float wg = wgt[i];
#pragma unroll
        for (int j = 0; j < 8; j++) {
            float4 v = *(const float4*)(src + j * 4);
            acc[j].x += wg * v.x; acc[j].y += wg * v.y;
            acc[j].z += wg * v.z; acc[j].w += wg * v.w;
        }
    }
    float* dst = out + ((size_t)b * T_ + qt * 64 + r) * HD_ + q4 * 32;
#pragma unroll
    for (int j = 0; j < 8; j++)
        *(float4*)(dst + j * 4) = make_float4(acc[j].x * invL, acc[j].y * invL,
                                              acc[j].z * invL, acc[j].w * invL);
}

// ---------------------------------------------------------------------------
extern "C" void kernel_launch(void* const* d_in, const int* in_sizes, int n_in,
                              void* d_out, int out_size) {
    const float* x  = (const float*)d_in[0];
    const float* Wq = (const float*)d_in[1];
    const float* Wk = (const float*)d_in[2];
    const float* Wv = (const float*)d_in[3];
    const float* rc = (const float*)d_in[4];
    const float* rs = (const float*)d_in[5];
    // d_in[6] = mask: causality applied analytically (identical result)
    float* out = (float*)d_out;

    const int smem_p1 = (64 * 132 + 64 * 132 + 64 * 136 + 64 * 68) * 4 + 256 * 4;
    cudaFuncSetAttribute(attn_p1, cudaFuncAttributeMaxDynamicSharedMemorySize, smem_p1);

    qkv_mma<<<dim3(64, 3), 256>>>(x, Wq, Wk, Wv, rc, rs);
    attn_p1<<<dim3(80, B_), 256, smem_p1>>>(out);
    attn_p2<<<dim3(24, B_), 256>>>(out);
}

// round 14
// speedup vs baseline: 1.4894x; 1.4894x over previous
#include <cuda_runtime.h>
#include <cstdint>
#include <math.h>

#define B_ 4
#define T_ 2048
#define EMB_ 2048
#define HD_ 128
#define HALF_ 64
#define SCALE_ 0.08838834764831845f   // 1/sqrt(128)

// __device__ scratch (allocation-free rule)
__device__ float g_Q[B_ * T_ * HD_];
__device__ float g_K[B_ * T_ * HD_];
__device__ float g_V[B_ * T_ * HD_];
// split-KV partials: [b][qt][chunk][64 rows][128] + m,l per row
__device__ float g_pO[B_ * 32 * 4 * 64 * HD_];
__device__ float g_pM[B_ * 32 * 4 * 64];
__device__ float g_pL[B_ * 32 * 4 * 64];

__device__ __forceinline__ uint32_t to_tf32_bits(float v) {
    uint32_t r;
    asm("{ .reg .b32 t; cvt.rna.tf32.f32 t, %1; mov.b32 %0, t; }" : "=r"(r) : "f"(v));
    return r;
}

__device__ __forceinline__ void mma_tf32(float* c, const uint32_t* a, const uint32_t* b) {
    asm volatile(
        "mma.sync.aligned.m16n8k8.row.col.f32.tf32.tf32.f32 "
        "{%0,%1,%2,%3}, {%4,%5,%6,%7}, {%8,%9}, {%0,%1,%2,%3};"
        : "+f"(c[0]), "+f"(c[1]), "+f"(c[2]), "+f"(c[3])
        : "r"(a[0]), "r"(a[1]), "r"(a[2]), "r"(a[3]), "r"(b[0]), "r"(b[1]));
}

// ---------------------------------------------------------------------------
// Kernel A: QKV projection via mma.sync tf32 + RoPE epilogue. (R8-exact:
// single-buffered, static smem, NO minBlocks cap — measured ~98us.)
// grid (64, 3). 256 threads = 8 warps (4M x 2N); warp tile 32x64.
// ---------------------------------------------------------------------------
__global__ __launch_bounds__(256) void qkv_mma(
    const float* __restrict__ x,  const float* __restrict__ Wq,
    const float* __restrict__ Wk, const float* __restrict__ Wv,
    const float* __restrict__ rc, const float* __restrict__ rs)
{
    __shared__ uint32_t As[128][36];   // [m][k], pad 36: frag loads bank 4*gid+tig
    __shared__ uint32_t Bs[32][136];   // [k][n], pad 136: frag loads bank 8*tig+gid

    const int which = blockIdx.y;
    const float* W = (which == 0) ? Wq : (which == 1) ? Wk : Wv;
    float* out     = (which == 0) ? g_Q : (which == 1) ? g_K : g_V;
    const int m0   = blockIdx.x * 128;

    const int tid  = threadIdx.x;
    const int wid  = tid >> 5, lane = tid & 31;
    const int gid  = lane >> 2, tig = lane & 3;
    const int wm   = (wid >> 1) * 32;     // warp row base
    const int wn   = (wid & 1) * 64;      // warp col base

    float acc[2][8][4];
#pragma unroll
    for (int mt = 0; mt < 2; mt++)
#pragma unroll
        for (int nt = 0; nt < 8; nt++)
#pragma unroll
            for (int q = 0; q < 4; q++) acc[mt][nt][q] = 0.f;

    for (int c = 0; c < 64; c++) {
        const float* xs = x + (size_t)m0 * EMB_ + c * 32;
        const float* ws = W + (size_t)(c * 32) * HD_;
#pragma unroll
        for (int it = 0; it < 4; it++) {
            int idx = it * 256 + tid;
            int m = idx >> 3, kk = (idx & 7) << 2;
            float4 v = *(const float4*)(xs + (size_t)m * EMB_ + kk);
            uint4 u = make_uint4(to_tf32_bits(v.x), to_tf32_bits(v.y),
                                 to_tf32_bits(v.z), to_tf32_bits(v.w));
            *(uint4*)&As[m][kk] = u;
        }
#pragma unroll
        for (int it = 0; it < 4; it++) {
            int idx = it * 256 + tid;
            int kk = idx >> 5, n = (idx & 31) << 2;
            float4 v = *(const float4*)(ws + (size_t)kk * HD_ + n);
            uint4 u = make_uint4(to_tf32_bits(v.x), to_tf32_bits(v.y),
                                 to_tf32_bits(v.z), to_tf32_bits(v.w));
            *(uint4*)&Bs[kk][n] = u;
        }
        __syncthreads();

#pragma unroll
        for (int s = 0; s < 4; s++) {          // K=8 slices
            const int kb = s * 8;
            uint32_t a[2][4], b[8][2];
#pragma unroll
            for (int mt = 0; mt < 2; mt++) {
                int mrow = wm + mt * 16 + gid;
                a[mt][0] = As[mrow][kb + tig];
                a[mt][1] = As[mrow + 8][kb + tig];
                a[mt][2] = As[mrow][kb + tig + 4];
                a[mt][3] = As[mrow + 8][kb + tig + 4];
            }
#pragma unroll
            for (int nt = 0; nt < 8; nt++) {
                int ncol = wn + nt * 8 + gid;
                b[nt][0] = Bs[kb + tig][ncol];
                b[nt][1] = Bs[kb + tig + 4][ncol];
            }
#pragma unroll
            for (int mt = 0; mt < 2; mt++)
#pragma unroll
                for (int nt = 0; nt < 8; nt++)
                    mma_tf32(acc[mt][nt], a[mt], b[nt]);
        }
        __syncthreads();
    }

    // Epilogue: RoPE pairs fall out of the C fragment layout.
#pragma unroll
    for (int mt = 0; mt < 2; mt++) {
#pragma unroll
        for (int half = 0; half < 2; half++) {
            int row = m0 + wm + mt * 16 + gid + half * 8;
            int t = row & (T_ - 1);
#pragma unroll
            for (int nt = 0; nt < 8; nt++) {
                int col = wn + nt * 8 + tig * 2;
                float re = acc[mt][nt][half * 2];
                float im = acc[mt][nt][half * 2 + 1];
                if (which < 2) {
                    float co = rc[t * HALF_ + (col >> 1)];
                    float si = rs[t * HALF_ + (col >> 1)];
                    float nre = re * co - im * si;
                    float nim = re * si + im * co;
                    re = nre; im = nim;
                }
                *(float2*)(out + (size_t)row * HD_ + col) = make_float2(re, im);
            }
        }
    }
}

// ---------------------------------------------------------------------------
// Kernel B1: flash attention phase 1 (R9-exact: mma.sync tf32, split-KV 512,
// 128 threads = 4 warps; warp w owns q-rows [16w,16w+16) — measured ~71us).
// grid (80, 4): x = work item (qt, chunk), y = batch.
// ---------------------------------------------------------------------------
__global__ __launch_bounds__(128) void attn_p1(float* __restrict__ out)
{
    extern __shared__ uint32_t dyn[];
    uint32_t* Qs = dyn;              // [64][132] tf32 bits
    uint32_t* Ks = Qs + 64 * 132;    // [64][132]
    uint32_t* Vs = Ks + 64 * 132;    // [64][136]
    uint32_t* Ps = Vs + 64 * 136;    // [64][68]

    const int tid = threadIdx.x;
    const int w = tid >> 5, lane = tid & 31;
    const int gid = lane >> 2, tig = lane & 3;
    const int b = blockIdx.y;
    const int i = blockIdx.x;

    int qt, c;
    if (i < 8)       { qt = i;                 c = 0; }
    else if (i < 24) { qt = 8 + (i - 8) / 2;   c = (i - 8) % 2; }
    else if (i < 48) { qt = 16 + (i - 24) / 3; c = (i - 24) % 3; }
    else             { qt = 24 + (i - 48) / 4; c = (i - 48) % 4; }
    const int kv_begin = c * 512;
    const int kv_end   = min((qt + 1) * 64, kv_begin + 512);
    const int niter    = (kv_end - kv_begin) >> 6;
    const int nch      = (qt >> 3) + 1;       // ceil((qt+1)/8)

    const float* gQ = g_Q + (size_t)b * T_ * HD_;
    const float* gK = g_K + (size_t)b * T_ * HD_;
    const float* gV = g_V + (size_t)b * T_ * HD_;

    // Load Q tile (scaled, tf32)
#pragma unroll
    for (int it = 0; it < 16; it++) {
        int idx = it * 128 + tid;
        int r = idx >> 5, c4 = idx & 31;
        float4 v = *(const float4*)(gQ + (size_t)(qt * 64 + r) * HD_ + c4 * 4);
        uint4 u = make_uint4(to_tf32_bits(v.x * SCALE_), to_tf32_bits(v.y * SCALE_),
                             to_tf32_bits(v.z * SCALE_), to_tf32_bits(v.w * SCALE_));
        *(uint4*)&Qs[r * 132 + c4 * 4] = u;
    }

    float o[16][4];
#pragma unroll
    for (int nt = 0; nt < 16; nt++)
#pragma unroll
        for (int q = 0; q < 4; q++) o[nt][q] = 0.f;
    float m0 = -1e30f, m1 = -1e30f, l0 = 0.f, l1 = 0.f;

    const int row0g = qt * 64 + w * 16 + gid;     // global q rows of this thread
    const int row1g = row0g + 8;

    for (int itkv = 0; itkv < niter; itkv++) {
        const int kv0 = kv_begin + itkv * 64;
        // load K, V tiles (tf32)
#pragma unroll
        for (int it = 0; it < 16; it++) {
            int idx = it * 128 + tid;
            int r = idx >> 5, c4 = idx & 31;
            float4 kv = *(const float4*)(gK + (size_t)(kv0 + r) * HD_ + c4 * 4);
            *(uint4*)&Ks[r * 132 + c4 * 4] =
                make_uint4(to_tf32_bits(kv.x), to_tf32_bits(kv.y),
                           to_tf32_bits(kv.z), to_tf32_bits(kv.w));
            float4 vv = *(const float4*)(gV + (size_t)(kv0 + r) * HD_ + c4 * 4);
            *(uint4*)&Vs[r * 136 + c4 * 4] =
                make_uint4(to_tf32_bits(vv.x), to_tf32_bits(vv.y),
                           to_tf32_bits(vv.z), to_tf32_bits(vv.w));
        }
        __syncthreads();

        // S = Q K^T : warp computes 16x64
        float s[8][4];
#pragma unroll
        for (int nt = 0; nt < 8; nt++)
#pragma unroll
            for (int q = 0; q < 4; q++) s[nt][q] = 0.f;
#pragma unroll
        for (int ks = 0; ks < 16; ks++) {
            uint32_t a[4];
            const int ar = (w * 16 + gid) * 132 + ks * 8 + tig;
            a[0] = Qs[ar];
            a[1] = Qs[ar + 8 * 132];
            a[2] = Qs[ar + 4];
            a[3] = Qs[ar + 8 * 132 + 4];
#pragma unroll
            for (int nt = 0; nt < 8; nt++) {
                uint32_t bfr[2];
                const int br = (nt * 8 + gid) * 132 + ks * 8 + tig;
                bfr[0] = Ks[br];
                bfr[1] = Ks[br + 4];
                mma_tf32(s[nt], a, bfr);
            }
        }

        // causal mask (only near the diagonal)
        if (kv0 + 63 > qt * 64 + w * 16) {
#pragma unroll
            for (int nt = 0; nt < 8; nt++) {
                int col = kv0 + nt * 8 + 2 * tig;
                if (col > row0g)     s[nt][0] = -1e30f;
                if (col + 1 > row0g) s[nt][1] = -1e30f;
                if (col > row1g)     s[nt][2] = -1e30f;
                if (col + 1 > row1g) s[nt][3] = -1e30f;
            }
        }

        // online softmax in fragments (rows spread over 4 tig lanes)
        float mr0 = -1e30f, mr1 = -1e30f;
#pragma unroll
        for (int nt = 0; nt < 8; nt++) {
            mr0 = fmaxf(mr0, fmaxf(s[nt][0], s[nt][1]));
            mr1 = fmaxf(mr1, fmaxf(s[nt][2], s[nt][3]));
        }
        mr0 = fmaxf(mr0, __shfl_xor_sync(0xffffffffu, mr0, 1));
        mr0 = fmaxf(mr0, __shfl_xor_sync(0xffffffffu, mr0, 2));
        mr1 = fmaxf(mr1, __shfl_xor_sync(0xffffffffu, mr1, 1));
        mr1 = fmaxf(mr1, __shfl_xor_sync(0xffffffffu, mr1, 2));
        float mn0 = fmaxf(m0, mr0), mn1 = fmaxf(m1, mr1);
        float al0 = __expf(m0 - mn0), al1 = __expf(m1 - mn1);
        float sum0 = 0.f, sum1 = 0.f;
#pragma unroll
        for (int nt = 0; nt < 8; nt++) {
            float p0 = __expf(s[nt][0] - mn0);
            float p1 = __expf(s[nt][1] - mn0);
            float p2 = __expf(s[nt][2] - mn1);
            float p3 = __expf(s[nt][3] - mn1);
            sum0 += p0 + p1; sum1 += p2 + p3;
            const int pc = nt * 8 + 2 * tig;
            *(uint2*)&Ps[(w * 16 + gid) * 68 + pc] =
                make_uint2(to_tf32_bits(p0), to_tf32_bits(p1));
            *(uint2*)&Ps[(w * 16 + gid + 8) * 68 + pc] =
                make_uint2(to_tf32_bits(p2), to_tf32_bits(p3));
        }
        sum0 += __shfl_xor_sync(0xffffffffu, sum0, 1);
        sum0 += __shfl_xor_sync(0xffffffffu, sum0, 2);
        sum1 += __shfl_xor_sync(0xffffffffu, sum1, 1);
        sum1 += __shfl_xor_sync(0xffffffffu, sum1, 2);
        l0 = l0 * al0 + sum0;  l1 = l1 * al1 + sum1;
        m0 = mn0;  m1 = mn1;
        __syncwarp();

        // rescale O, then O += P @ V
#pragma unroll
        for (int nt = 0; nt < 16; nt++) {
            o[nt][0] *= al0; o[nt][1] *= al0;
            o[nt][2] *= al1; o[nt][3] *= al1;
        }
#pragma unroll
        for (int ks = 0; ks < 8; ks++) {
            uint32_t a[4];
            const int ar = (w * 16 + gid) * 68 + ks * 8 + tig;
            a[0] = Ps[ar];
            a[1] = Ps[ar + 8 * 68];
            a[2] = Ps[ar + 4];
            a[3] = Ps[ar + 8 * 68 + 4];
#pragma unroll
            for (int nt = 0; nt < 16; nt++) {
                uint32_t bfr[2];
                const int br = (ks * 8 + tig) * 136 + nt * 8 + gid;
                bfr[0] = Vs[br];
                bfr[1] = Vs[br + 4 * 136];
                mma_tf32(o[nt], a, bfr);
            }
        }
        __syncthreads();
    }

    // epilogue
    const int rl0 = w * 16 + gid, rl1 = rl0 + 8;
    if (nch == 1) {
        float inv0 = 1.f / l0, inv1 = 1.f / l1;
        float* dst = out + (size_t)b * T_ * HD_;
#pragma unroll
        for (int nt = 0; nt < 16; nt++) {
            int col = nt * 8 + 2 * tig;
            *(float2*)(dst + (size_t)(qt * 64 + rl0) * HD_ + col) =
                make_float2(o[nt][0] * inv0, o[nt][1] * inv0);
            *(float2*)(dst + (size_t)(qt * 64 + rl1) * HD_ + col) =
                make_float2(o[nt][2] * inv1, o[nt][3] * inv1);
        }
    } else {
        const size_t sb = ((size_t)((b * 32 + qt) * 4 + c)) * 64;
        float* pO = g_pO + sb * HD_;
#pragma unroll
        for (int nt = 0; nt < 16; nt++) {
            int col = nt * 8 + 2 * tig;
            *(float2*)(pO + (size_t)rl0 * HD_ + col) = make_float2(o[nt][0], o[nt][1]);
            *(float2*)(pO + (size_t)rl1 * HD_ + col) = make_float2(o[nt][2], o[nt][3]);
        }
        if (tig == 0) {
            g_pM[sb + rl0] = m0;  g_pL[sb + rl0] = l0;
            g_pM[sb + rl1] = m1;  g_pL[sb + rl1] = l1;
        }
    }
}

// ---------------------------------------------------------------------------
// Kernel B2: combine split-KV partials for qt >= 8. grid (24, 4), 256 threads.
// ---------------------------------------------------------------------------
__global__ __launch_bounds__(256) void attn_p2(float* __restrict__ out)
{
    const int qt = 8 + blockIdx.x;
    const int b  = blockIdx.y;
    const int nch = (qt >> 3) + 1;          // 2..4
    const int tid = threadIdx.x;
    const int r = tid >> 2, q4 = tid & 3;

    const size_t mlb = ((size_t)(b * 32 + qt) * 4) * 64 + r;
    float mv[4], lv[4];
    float M = -1e30f;
    for (int i = 0; i < nch; i++) {
        mv[i] = g_pM[mlb + (size_t)i * 64];
        lv[i] = g_pL[mlb + (size_t)i * 64];
        M = fmaxf(M, mv[i]);
    }
    float L = 0.f, wgt[4];
    for (int i = 0; i < nch; i++) {
        wgt[i] = __expf(mv[i] - M);
        L += wgt[i] * lv[i];
    }
    const float invL = 1.f / L;

    float4 acc[8];
#pragma unroll
    for (int j = 0; j < 8; j++) acc[j] = make_float4(0.f, 0.f, 0.f, 0.f);
    for (int i = 0; i < nch; i++) {
        const float* src = g_pO +
            (((size_t)((b * 32 + qt) * 4 + i)) * 64 + r) * HD_ + q4 * 32;
        float wg = wgt[i];
#pragma unroll
        for (int j = 0; j < 8; j++) {
            float4 v = *(const float4*)(src + j * 4);
            acc[j].x += wg * v.x; acc[j].y += wg * v.y;
            acc[j].z += wg * v.z; acc[j].w += wg * v.w;
        }
    }
    float* dst = out + ((size_t)b * T_ + qt * 64 + r) * HD_ + q4 * 32;
#pragma unroll
    for (int j = 0; j < 8; j++)
        *(float4*)(dst + j * 4) = make_float4(acc[j].x * invL, acc[j].y * invL,
                                              acc[j].z * invL, acc[j].w * invL);
}

// ---------------------------------------------------------------------------
extern "C" void kernel_launch(void* const* d_in, const int* in_sizes, int n_in,
                              void* d_out, int out_size) {
    const float* x  = (const float*)d_in[0];
    const float* Wq = (const float*)d_in[1];
    const float* Wk = (const float*)d_in[2];
    const float* Wv = (const float*)d_in[3];
    const float* rc = (const float*)d_in[4];
    const float* rs = (const float*)d_in[5];
    // d_in[6] = mask: causality applied analytically (identical result)
    float* out = (float*)d_out;

    const int smem_p1 = (64 * 132 + 64 * 132 + 64 * 136 + 64 * 68) * 4; // 119808
    cudaFuncSetAttribute(attn_p1, cudaFuncAttributeMaxDynamicSharedMemorySize, smem_p1);

    qkv_mma<<<dim3(64, 3), 256>>>(x, Wq, Wk, Wv, rc, rs);
    attn_p1<<<dim3(80, B_), 128, smem_p1>>>(out);
    attn_p2<<<dim3(24, B_), 256>>>(out);
}